// round 14
// baseline (speedup 1.0000x reference)
#include <cuda_runtime.h>
#include <cuda_bf16.h>
#include <mma.h>
#include <math.h>
#include <stdint.h>

using namespace nvcuda;

#define NN 100000
#define EMAX 1048576
#define SCAN_BLK 512
#define NSCAN ((NN + SCAN_BLK - 1) / SCAN_BLK)   // 196

// ---------------- scratch (static device globals; no allocation) ----------------
__device__ float g_inv[NN];
__device__ int   g_cnt[NN];
__device__ int   g_rowstart[NN];
__device__ int   g_cursor[NN];
__device__ int   g_csr[EMAX];
__device__ int   g_bsum[NSCAN];
__device__ int   g_boff[SCAN_BLK];
__device__ float g_ts[NN * 256];               // layer2 GEMM out: [t | s]
__device__ float g_u[NN * 128];                // layer3 GEMM out: [u_l | u_r]
__device__ __nv_bfloat16 g_A1[(size_t)NN * 512];  // [catHi(256) | catLo(256)]
__device__ __nv_bfloat16 g_A2[(size_t)NN * 512];  // [h1Hi | h1Lo]
__device__ __nv_bfloat16 g_A3[(size_t)NN * 256];  // [h2Hi | h2Lo]
__device__ __nv_bfloat16 g_B1t[256 * 512];     // B1^T: [hi(256) | lo(256)] per row
__device__ __nv_bfloat16 g_B2t[256 * 512];
__device__ __nv_bfloat16 g_B3t[128 * 256];

// ---------------- cp.async helpers (portable sm_80+ PTX) ----------------
__device__ __forceinline__ uint32_t smem_u32(const void* p) {
    uint32_t a;
    asm("{ .reg .u64 t; cvta.to.shared.u64 t, %1; cvt.u32.u64 %0, t; }" : "=r"(a) : "l"(p));
    return a;
}
__device__ __forceinline__ void cp_async16(uint32_t s, const void* g) {
    asm volatile("cp.async.cg.shared.global [%0], [%1], 16;" :: "r"(s), "l"(g) : "memory");
}
__device__ __forceinline__ void cp_commit() {
    asm volatile("cp.async.commit_group;" ::: "memory");
}
template <int N>
__device__ __forceinline__ void cp_wait() {
    asm volatile("cp.async.wait_group %0;" :: "n"(N) : "memory");
}

// ---------------- CSR build ----------------
__global__ void zero_int2() {
    int i = blockIdx.x * blockDim.x + threadIdx.x;
    if (i < NN) { g_cnt[i] = 0; g_cursor[i] = 0; }
}
__global__ void count_kernel(const int* __restrict__ ei, int E) {
    int e = blockIdx.x * blockDim.x + threadIdx.x;
    if (e < E) atomicAdd(&g_cnt[ei[E + e]], 1);
}
__global__ void inv_kernel() {
    int n = blockIdx.x * blockDim.x + threadIdx.x;
    if (n < NN) g_inv[n] = 1.0f / (float)max(g_cnt[n], 1);
}
__global__ void scan1_kernel() {
    __shared__ int s[SCAN_BLK];
    int tid = threadIdx.x;
    int i = blockIdx.x * SCAN_BLK + tid;
    int v = (i < NN) ? g_cnt[i] : 0;
    s[tid] = v;
    __syncthreads();
    #pragma unroll
    for (int off = 1; off < SCAN_BLK; off <<= 1) {
        int t = (tid >= off) ? s[tid - off] : 0;
        __syncthreads();
        s[tid] += t;
        __syncthreads();
    }
    if (i < NN) g_rowstart[i] = s[tid] - v;
    if (tid == SCAN_BLK - 1) g_bsum[blockIdx.x] = s[tid];
}
__global__ void scan2_kernel() {
    __shared__ int s[SCAN_BLK];
    int tid = threadIdx.x;
    int v = (tid < NSCAN) ? g_bsum[tid] : 0;
    s[tid] = v;
    __syncthreads();
    #pragma unroll
    for (int off = 1; off < SCAN_BLK; off <<= 1) {
        int t = (tid >= off) ? s[tid - off] : 0;
        __syncthreads();
        s[tid] += t;
        __syncthreads();
    }
    g_boff[tid] = s[tid] - v;
}
__global__ void scan3_kernel() {
    int i = blockIdx.x * blockDim.x + threadIdx.x;
    if (i < NN) g_rowstart[i] += g_boff[i / SCAN_BLK];
}
__global__ void fill_kernel(const int* __restrict__ ei, int E) {
    int e = blockIdx.x * blockDim.x + threadIdx.x;
    if (e >= E) return;
    int d = ei[E + e];
    int pos = atomicAdd(&g_cursor[d], 1);
    g_csr[g_rowstart[d] + pos] = ei[e];
}

// ---------------- split helpers ----------------
__device__ __forceinline__ void split4(float4 v, uint2& hi, uint2& lo) {
    __nv_bfloat16 h[4], l[4];
    float f[4] = {v.x, v.y, v.z, v.w};
    #pragma unroll
    for (int j = 0; j < 4; j++) {
        h[j] = __float2bfloat16(f[j]);
        l[j] = __float2bfloat16(f[j] - __bfloat162float(h[j]));
    }
    hi = *(uint2*)h;
    lo = *(uint2*)l;
}
__device__ __forceinline__ void split8(const float* v, __nv_bfloat16* hi, __nv_bfloat16* lo) {
    #pragma unroll
    for (int j = 0; j < 8; j++) {
        hi[j] = __float2bfloat16(v[j]);
        lo[j] = __float2bfloat16(v[j] - __bfloat162float(hi[j]));
    }
}

// ---------------- B^T split builders: rows [hi(K) | lo(K)] ----------------
__global__ void build_b1t(const float* __restrict__ W1l, const float* __restrict__ W1r) {
    int idx = blockIdx.x * blockDim.x + threadIdx.x;
    if (idx >= 256 * 512) return;
    int n = idx >> 9, kk = idx & 511;
    int seg = kk >> 8, k = kk & 255;
    float w = (k < 128) ? W1l[k * 256 + n] : W1r[(k - 128) * 256 + n];
    __nv_bfloat16 hi = __float2bfloat16(w);
    g_B1t[idx] = seg ? __float2bfloat16(w - __bfloat162float(hi)) : hi;
}
__global__ void build_b2t(const float* __restrict__ W2l, const float* __restrict__ W2r) {
    int idx = blockIdx.x * blockDim.x + threadIdx.x;
    if (idx >= 256 * 512) return;
    int n = idx >> 9, kk = idx & 511;
    int seg = kk >> 8, k = kk & 255;
    float w = (n < 128) ? W2l[k * 128 + n] : W2r[k * 128 + (n - 128)];
    __nv_bfloat16 hi = __float2bfloat16(w);
    g_B2t[idx] = seg ? __float2bfloat16(w - __bfloat162float(hi)) : hi;
}
__global__ void build_b3t(const float* __restrict__ W3l, const float* __restrict__ W3r) {
    int idx = blockIdx.x * blockDim.x + threadIdx.x;
    if (idx >= 128 * 256) return;
    int n = idx >> 8, kk = idx & 255;
    int seg = kk >> 7, k = kk & 127;
    float w = (n < 64) ? W3l[k * 64 + n] : W3r[k * 64 + (n - 64)];
    __nv_bfloat16 hi = __float2bfloat16(w);
    g_B3t[idx] = seg ? __float2bfloat16(w - __bfloat162float(hi)) : hi;
}

// ---------------- g1: gather-mean(x) + self + split -> A1 [hi(256)|lo(256)] ------
// one warp per node; lane owns float4 column `lane` of 32.
__global__ void g1_fused(const float* __restrict__ x) {
    int gw = (blockIdx.x * blockDim.x + threadIdx.x) >> 5;
    int lane = threadIdx.x & 31;
    if (gw >= NN) return;
    int beg = g_rowstart[gw], cnt = g_cnt[gw];
    const int* cs = g_csr + beg;
    float4 acc = make_float4(0.f, 0.f, 0.f, 0.f);
    for (int i = 0; i < cnt; i++) {
        int s = __ldg(&cs[i]);
        float4 v = __ldg((const float4*)x + (size_t)s * 32 + lane);
        acc.x += v.x; acc.y += v.y; acc.z += v.z; acc.w += v.w;
    }
    float inv = g_inv[gw];
    acc.x *= inv; acc.y *= inv; acc.z *= inv; acc.w *= inv;
    float4 xv = __ldg((const float4*)x + (size_t)gw * 32 + lane);
    uint2 mh, ml, xh, xl;
    split4(acc, mh, ml);
    split4(xv, xh, xl);
    __nv_bfloat16* row = g_A1 + (size_t)gw * 512;
    *(uint2*)(row + lane * 4)       = mh;   // mean hi  (cols 0-127)
    *(uint2*)(row + 128 + lane * 4) = xh;   // x hi     (cols 128-255)
    *(uint2*)(row + 256 + lane * 4) = ml;   // mean lo
    *(uint2*)(row + 384 + lane * 4) = xl;   // x lo
}

// ---------------- g2: gather-mean(t) + s + b2 + relu + split -> A3 [hi|lo] -------
__global__ void g2_fused(const float* __restrict__ b2) {
    int gw = (blockIdx.x * blockDim.x + threadIdx.x) >> 5;
    int lane = threadIdx.x & 31;
    if (gw >= NN) return;
    int beg = g_rowstart[gw], cnt = g_cnt[gw];
    const int* cs = g_csr + beg;
    float4 acc = make_float4(0.f, 0.f, 0.f, 0.f);
    for (int i = 0; i < cnt; i++) {
        int s = __ldg(&cs[i]);
        float4 v = __ldg((const float4*)g_ts + (size_t)s * 64 + lane);
        acc.x += v.x; acc.y += v.y; acc.z += v.z; acc.w += v.w;
    }
    float inv = g_inv[gw];
    float4 sv = __ldg((const float4*)g_ts + (size_t)gw * 64 + 32 + lane);
    float4 bb = __ldg((const float4*)b2 + lane);
    float4 r;
    r.x = fmaxf(acc.x * inv + sv.x + bb.x, 0.f);
    r.y = fmaxf(acc.y * inv + sv.y + bb.y, 0.f);
    r.z = fmaxf(acc.z * inv + sv.z + bb.z, 0.f);
    r.w = fmaxf(acc.w * inv + sv.w + bb.w, 0.f);
    uint2 hi, lo;
    split4(r, hi, lo);
    __nv_bfloat16* row = g_A3 + (size_t)gw * 256;
    *(uint2*)(row + lane * 4)       = hi;
    *(uint2*)(row + 128 + lane * 4) = lo;
}

// ---------------- g3: gather-mean(u_l) + u_r + b3 + log_softmax -> out ----------
// one warp per node; lane owns float2 cols {2l, 2l+1} of 64.
__global__ void g3_fused(const float* __restrict__ b3, float* __restrict__ out) {
    int gw = (blockIdx.x * blockDim.x + threadIdx.x) >> 5;
    int lane = threadIdx.x & 31;
    if (gw >= NN) return;
    int beg = g_rowstart[gw], cnt = g_cnt[gw];
    const int* cs = g_csr + beg;
    float2 acc = make_float2(0.f, 0.f);
    for (int i = 0; i < cnt; i++) {
        int s = __ldg(&cs[i]);
        float2 v = __ldg((const float2*)g_u + (size_t)s * 64 + lane);
        acc.x += v.x; acc.y += v.y;
    }
    float inv = g_inv[gw];
    float2 ur = __ldg((const float2*)g_u + (size_t)gw * 64 + 32 + lane);
    float2 bv = __ldg((const float2*)b3 + lane);
    float v0 = acc.x * inv + ur.x + bv.x;
    float v1 = acc.y * inv + ur.y + bv.y;
    float m = fmaxf(v0, v1);
    #pragma unroll
    for (int o = 16; o; o >>= 1) m = fmaxf(m, __shfl_xor_sync(0xffffffffu, m, o));
    float sum = expf(v0 - m) + expf(v1 - m);
    #pragma unroll
    for (int o = 16; o; o >>= 1) sum += __shfl_xor_sync(0xffffffffu, sum, o);
    float lse = m + logf(sum);
    float2 res = make_float2(v0 - lse, v1 - lse);
    *((float2*)out + (size_t)gw * 32 + lane) = res;
}

// ---------------- wmma bf16 GEMM, 2-stage cp.async pipeline, chunk-mapped --------
// A,Bt physical layout: [hi(K) | lo(K)] per row, stride Kst = 2K elements.
// Logical chunks j in [0, 3*KC): j<KC -> (Ahi_j, Bhi_j); j<2KC -> (Ahi, Blo);
// else -> (Alo, Bhi).  KC = K/64 physical hi chunks.
#define LDT 72
#define TILE_B (128 * LDT * 2)
#define GEMM_SMEM (2 * 2 * TILE_B)   // 73728 bytes

__device__ __forceinline__ void chunkmap(int j, int KC, int& ca, int& cb) {
    if (j < KC)          { ca = j;      cb = j; }
    else if (j < 2 * KC) { ca = j - KC; cb = j; }
    else                 { ca = j - KC; cb = j - 2 * KC; }
}

__global__ __launch_bounds__(256) void gemm_wmma(
    const __nv_bfloat16* __restrict__ A, const __nv_bfloat16* __restrict__ Bt,
    float* __restrict__ Cf, __nv_bfloat16* __restrict__ Chl,
    const float* __restrict__ bias, int M, int Nfull, int KC, int mode, int relu)
{
    extern __shared__ __align__(16) uint8_t dynsmem[];
    float* stage = (float*)dynsmem;   // epilogue overlay (128 x 68 f32)
    const int LDS = 68;

    const int tid = threadIdx.x;
    const int wid = tid >> 5;
    const int wr = wid >> 2, wc = wid & 3;
    const int blockRow = blockIdx.y * 128;
    const int n0 = blockIdx.x * 128;
    const int Kst = KC * 128;          // physical row stride in elements
    const int NCL = 3 * KC;

    wmma::fragment<wmma::accumulator, 16, 16, 16, float> acc[4][2];
    #pragma unroll
    for (int i = 0; i < 4; i++)
        #pragma unroll
        for (int j = 0; j < 2; j++) wmma::fill_fragment(acc[i][j], 0.f);

    auto issue = [&](int j, int st) {
        int ca, cb;
        chunkmap(j, KC, ca, cb);
        uint8_t* bufA = dynsmem + st * 2 * TILE_B;
        uint8_t* bufB = bufA + TILE_B;
        #pragma unroll
        for (int i = 0; i < 4; i++) {
            int idx = tid + i * 256;
            int r = idx >> 3, c16 = idx & 7;
            int grow = blockRow + r; if (grow >= M) grow = M - 1;
            cp_async16(smem_u32(bufA + (r * LDT + c16 * 8) * 2),
                       A + (size_t)grow * Kst + (size_t)ca * 64 + c16 * 8);
            int nrow = n0 + r;
            cp_async16(smem_u32(bufB + (r * LDT + c16 * 8) * 2),
                       Bt + (size_t)nrow * Kst + (size_t)cb * 64 + c16 * 8);
        }
        cp_commit();
    };

    issue(0, 0);
    for (int c = 0; c < NCL; c++) {
        int st = c & 1;
        if (c + 1 < NCL) { issue(c + 1, (c + 1) & 1); cp_wait<1>(); }
        else             { cp_wait<0>(); }
        __syncthreads();
        __nv_bfloat16* sA = (__nv_bfloat16*)(dynsmem + st * 2 * TILE_B);
        __nv_bfloat16* sB = (__nv_bfloat16*)(dynsmem + st * 2 * TILE_B + TILE_B);
        #pragma unroll
        for (int k = 0; k < 4; k++) {
            wmma::fragment<wmma::matrix_a, 16, 16, 16, __nv_bfloat16, wmma::row_major> af[4];
            wmma::fragment<wmma::matrix_b, 16, 16, 16, __nv_bfloat16, wmma::col_major> bf[2];
            #pragma unroll
            for (int i = 0; i < 4; i++)
                wmma::load_matrix_sync(af[i], sA + (wr * 64 + i * 16) * LDT + k * 16, LDT);
            #pragma unroll
            for (int j = 0; j < 2; j++)
                wmma::load_matrix_sync(bf[j], sB + (wc * 32 + j * 16) * LDT + k * 16, LDT);
            #pragma unroll
            for (int i = 0; i < 4; i++)
                #pragma unroll
                for (int j = 0; j < 2; j++)
                    wmma::mma_sync(acc[i][j], af[i], bf[j], acc[i][j]);
        }
        __syncthreads();
    }

    // epilogue: two passes of 64 N-columns through the smem stage
    for (int p = 0; p < 2; p++) {
        __syncthreads();
        if ((wc >> 1) == p) {
            #pragma unroll
            for (int i = 0; i < 4; i++)
                #pragma unroll
                for (int j = 0; j < 2; j++)
                    wmma::store_matrix_sync(
                        stage + (wr * 64 + i * 16) * LDS + (wc & 1) * 32 + j * 16,
                        acc[i][j], LDS, wmma::mem_row_major);
        }
        __syncthreads();
        int r = tid >> 1, h = tid & 1;
        int grow = blockRow + r;
        if (grow < M) {
            #pragma unroll
            for (int g = 0; g < 4; g++) {
                int cl = h * 32 + g * 8;
                int gcol = n0 + p * 64 + cl;
                float v[8];
                #pragma unroll
                for (int j = 0; j < 8; j++) {
                    v[j] = stage[r * LDS + cl + j];
                    if (bias) v[j] += __ldg(&bias[gcol + j]);
                    if (relu) v[j] = fmaxf(v[j], 0.f);
                }
                if (mode == 0) {
                    float4* pp = (float4*)(Cf + (size_t)grow * Nfull + gcol);
                    pp[0] = make_float4(v[0], v[1], v[2], v[3]);
                    pp[1] = make_float4(v[4], v[5], v[6], v[7]);
                } else {
                    alignas(16) __nv_bfloat16 hi[8], lo[8];
                    split8(v, hi, lo);
                    __nv_bfloat16* base = Chl + (size_t)grow * (2 * Nfull) + gcol;
                    *(uint4*)(base)         = *(uint4*)hi;
                    *(uint4*)(base + Nfull) = *(uint4*)lo;
                }
            }
        }
    }
}

// ---------------- launch ----------------
extern "C" void kernel_launch(void* const* d_in, const int* in_sizes, int n_in,
                              void* d_out, int out_size) {
    const float* x   = (const float*)d_in[0];
    const int*   ei  = (const int*)d_in[1];     // int32 edge_index [2, E]
    const float* W1l = (const float*)d_in[2];
    const float* W1r = (const float*)d_in[3];
    const float* b1  = (const float*)d_in[4];
    const float* W2l = (const float*)d_in[5];
    const float* W2r = (const float*)d_in[6];
    const float* b2  = (const float*)d_in[7];
    const float* W3l = (const float*)d_in[8];
    const float* W3r = (const float*)d_in[9];
    const float* b3  = (const float*)d_in[10];
    float* out = (float*)d_out;
    int E = in_sizes[1] / 2;
    (void)n_in; (void)out_size;

    void *p_ts, *p_u, *p_A1, *p_A2, *p_A3, *p_B1t, *p_B2t, *p_B3t;
    cudaGetSymbolAddress(&p_ts, g_ts);
    cudaGetSymbolAddress(&p_u, g_u);
    cudaGetSymbolAddress(&p_A1, g_A1);
    cudaGetSymbolAddress(&p_A2, g_A2);
    cudaGetSymbolAddress(&p_A3, g_A3);
    cudaGetSymbolAddress(&p_B1t, g_B1t);
    cudaGetSymbolAddress(&p_B2t, g_B2t);
    cudaGetSymbolAddress(&p_B3t, g_B3t);

    cudaFuncSetAttribute(gemm_wmma, cudaFuncAttributeMaxDynamicSharedMemorySize, GEMM_SMEM);

    const int MT = (NN + 127) / 128;   // 782 M-tiles

    // ---- CSR build (once; shared by all 3 aggregations) ----
    zero_int2<<<(NN + 255) / 256, 256>>>();
    count_kernel<<<(E + 255) / 256, 256>>>(ei, E);
    inv_kernel<<<(NN + 255) / 256, 256>>>();
    scan1_kernel<<<NSCAN, SCAN_BLK>>>();
    scan2_kernel<<<1, SCAN_BLK>>>();
    scan3_kernel<<<(NN + 255) / 256, 256>>>();
    fill_kernel<<<(E + 255) / 256, 256>>>(ei, E);

    build_b1t<<<(256 * 512 + 255) / 256, 256>>>(W1l, W1r);
    build_b2t<<<(256 * 512 + 255) / 256, 256>>>(W2l, W2r);
    build_b3t<<<(128 * 256 + 255) / 256, 256>>>(W3l, W3r);

    // ---- layer 1: fused gather+cat+split -> A1, GEMM1 -> A2 (split out) ----
    g1_fused<<<(NN * 32 + 255) / 256, 256>>>(x);
    gemm_wmma<<<dim3(2, MT), 256, GEMM_SMEM>>>(
        (const __nv_bfloat16*)p_A1, (const __nv_bfloat16*)p_B1t,
        nullptr, (__nv_bfloat16*)p_A2, b1, NN, 256, 4, 1, 1);

    // ---- layer 2: GEMM2 -> [t|s], fused gather+combine+split -> A3 ----
    gemm_wmma<<<dim3(2, MT), 256, GEMM_SMEM>>>(
        (const __nv_bfloat16*)p_A2, (const __nv_bfloat16*)p_B2t,
        (float*)p_ts, nullptr, nullptr, NN, 256, 4, 0, 0);
    g2_fused<<<(NN * 32 + 255) / 256, 256>>>(b2);

    // ---- layer 3: GEMM3 -> [u_l|u_r], fused gather+final ----
    gemm_wmma<<<dim3(1, MT), 256, GEMM_SMEM>>>(
        (const __nv_bfloat16*)p_A3, (const __nv_bfloat16*)p_B3t,
        (float*)p_u, nullptr, nullptr, NN, 128, 2, 0, 0);
    g3_fused<<<(NN * 32 + 255) / 256, 256>>>(b3, out);
}

// round 16
// speedup vs baseline: 1.0646x; 1.0646x over previous
#include <cuda_runtime.h>
#include <cuda_bf16.h>
#include <mma.h>
#include <math.h>
#include <stdint.h>

using namespace nvcuda;

#define NN 100000
#define EMAX 1048576
#define SCAN_BLK 512
#define NSCAN ((NN + SCAN_BLK - 1) / SCAN_BLK)   // 196

// ---------------- scratch (static device globals; no allocation) ----------------
__device__ float g_inv[NN];
__device__ int   g_cnt[NN];
__device__ int   g_rowstart[NN];
__device__ int   g_cursor[NN];
__device__ int   g_csr[EMAX];
__device__ int   g_bsum[NSCAN];
__device__ int   g_boff[SCAN_BLK];
__device__ float g_agg[NN * 128];              // layer1: mean(x), layer2: mean(t)
__device__ float g_agg3[NN * 64];              // layer3 mean
__device__ float g_ts[NN * 256];               // layer2 GEMM out: [t | s]
__device__ float g_u[NN * 128];                // layer3 GEMM out: [u_l | u_r]
__device__ __nv_bfloat16 g_A1[(size_t)NN * 768];  // [catHi | catHi | catLo]
__device__ __nv_bfloat16 g_A2[(size_t)NN * 768];  // [h1Hi | h1Hi | h1Lo]
__device__ __nv_bfloat16 g_A3[(size_t)NN * 384];  // [h2Hi | h2Hi | h2Lo]
__device__ __nv_bfloat16 g_B1t[256 * 768];     // B1^T split: [hi | lo | hi]
__device__ __nv_bfloat16 g_B2t[256 * 768];
__device__ __nv_bfloat16 g_B3t[128 * 384];

// ---------------- cp.async helpers (portable sm_80+ PTX) ----------------
__device__ __forceinline__ uint32_t smem_u32(const void* p) {
    uint32_t a;
    asm("{ .reg .u64 t; cvta.to.shared.u64 t, %1; cvt.u32.u64 %0, t; }" : "=r"(a) : "l"(p));
    return a;
}
__device__ __forceinline__ void cp_async16(uint32_t s, const void* g) {
    asm volatile("cp.async.cg.shared.global [%0], [%1], 16;" :: "r"(s), "l"(g) : "memory");
}
__device__ __forceinline__ void cp_commit() {
    asm volatile("cp.async.commit_group;" ::: "memory");
}
template <int N>
__device__ __forceinline__ void cp_wait() {
    asm volatile("cp.async.wait_group %0;" :: "n"(N) : "memory");
}

// ---------------- CSR build ----------------
__global__ void zero_int2() {
    int i = blockIdx.x * blockDim.x + threadIdx.x;
    if (i < NN) { g_cnt[i] = 0; g_cursor[i] = 0; }
}
__global__ void count_kernel(const int* __restrict__ ei, int E) {
    int e = blockIdx.x * blockDim.x + threadIdx.x;
    if (e < E) atomicAdd(&g_cnt[ei[E + e]], 1);
}
__global__ void inv_kernel() {
    int n = blockIdx.x * blockDim.x + threadIdx.x;
    if (n < NN) g_inv[n] = 1.0f / (float)max(g_cnt[n], 1);
}
__global__ void scan1_kernel() {
    __shared__ int s[SCAN_BLK];
    int tid = threadIdx.x;
    int i = blockIdx.x * SCAN_BLK + tid;
    int v = (i < NN) ? g_cnt[i] : 0;
    s[tid] = v;
    __syncthreads();
    #pragma unroll
    for (int off = 1; off < SCAN_BLK; off <<= 1) {
        int t = (tid >= off) ? s[tid - off] : 0;
        __syncthreads();
        s[tid] += t;
        __syncthreads();
    }
    if (i < NN) g_rowstart[i] = s[tid] - v;
    if (tid == SCAN_BLK - 1) g_bsum[blockIdx.x] = s[tid];
}
__global__ void scan2_kernel() {
    __shared__ int s[SCAN_BLK];
    int tid = threadIdx.x;
    int v = (tid < NSCAN) ? g_bsum[tid] : 0;
    s[tid] = v;
    __syncthreads();
    #pragma unroll
    for (int off = 1; off < SCAN_BLK; off <<= 1) {
        int t = (tid >= off) ? s[tid - off] : 0;
        __syncthreads();
        s[tid] += t;
        __syncthreads();
    }
    g_boff[tid] = s[tid] - v;
}
__global__ void scan3_kernel() {
    int i = blockIdx.x * blockDim.x + threadIdx.x;
    if (i < NN) g_rowstart[i] += g_boff[i / SCAN_BLK];
}
__global__ void fill_kernel(const int* __restrict__ ei, int E) {
    int e = blockIdx.x * blockDim.x + threadIdx.x;
    if (e >= E) return;
    int d = ei[E + e];
    int pos = atomicAdd(&g_cursor[d], 1);
    g_csr[g_rowstart[d] + pos] = ei[e];
}

// ---------------- gather-mean: dst[n] = (1/deg) * sum_{s in N(n)} src[s] ----------
template <int C4>
__global__ void gather_mean(const float* __restrict__ src, int srcStride4,
                            float* __restrict__ dst) {
    constexpr int NPW = 32 / C4;
    int gw = (blockIdx.x * blockDim.x + threadIdx.x) >> 5;
    int lane = threadIdx.x & 31;
    int node = gw * NPW + lane / C4;
    int col = lane % C4;
    if (node >= NN) return;
    int beg = g_rowstart[node];
    int cnt = g_cnt[node];
    const int* cs = g_csr + beg;
    float4 acc = make_float4(0.f, 0.f, 0.f, 0.f);
    for (int i = 0; i < cnt; i++) {
        int s = __ldg(&cs[i]);
        float4 v = __ldg((const float4*)src + (size_t)s * srcStride4 + col);
        acc.x += v.x; acc.y += v.y; acc.z += v.z; acc.w += v.w;
    }
    float inv = g_inv[node];
    acc.x *= inv; acc.y *= inv; acc.z *= inv; acc.w *= inv;
    ((float4*)dst)[(size_t)node * C4 + col] = acc;
}

// ---------------- B^T split builders: segments [hi | lo | hi] ----------------
__global__ void build_b1t(const float* __restrict__ W1l, const float* __restrict__ W1r) {
    int idx = blockIdx.x * blockDim.x + threadIdx.x;
    if (idx >= 256 * 768) return;
    int n = idx / 768, k3 = idx - n * 768;
    int seg = k3 >> 8, k = k3 & 255;
    float w = (k < 128) ? W1l[k * 256 + n] : W1r[(k - 128) * 256 + n];
    __nv_bfloat16 hi = __float2bfloat16(w);
    g_B1t[idx] = (seg == 1) ? __float2bfloat16(w - __bfloat162float(hi)) : hi;
}
__global__ void build_b2t(const float* __restrict__ W2l, const float* __restrict__ W2r) {
    int idx = blockIdx.x * blockDim.x + threadIdx.x;
    if (idx >= 256 * 768) return;
    int n = idx / 768, k3 = idx - n * 768;
    int seg = k3 >> 8, k = k3 & 255;
    float w = (n < 128) ? W2l[k * 128 + n] : W2r[k * 128 + (n - 128)];
    __nv_bfloat16 hi = __float2bfloat16(w);
    g_B2t[idx] = (seg == 1) ? __float2bfloat16(w - __bfloat162float(hi)) : hi;
}
__global__ void build_b3t(const float* __restrict__ W3l, const float* __restrict__ W3r) {
    int idx = blockIdx.x * blockDim.x + threadIdx.x;
    if (idx >= 128 * 384) return;
    int n = idx / 384, k3 = idx - n * 384;
    int seg = k3 >> 7, k = k3 & 127;
    float w = (n < 64) ? W3l[k * 64 + n] : W3r[k * 64 + (n - 64)];
    __nv_bfloat16 hi = __float2bfloat16(w);
    g_B3t[idx] = (seg == 1) ? __float2bfloat16(w - __bfloat162float(hi)) : hi;
}

// ---------------- split helper ----------------
__device__ __forceinline__ void split8(const float* v, __nv_bfloat16* hi, __nv_bfloat16* lo) {
    #pragma unroll
    for (int j = 0; j < 8; j++) {
        hi[j] = __float2bfloat16(v[j]);
        lo[j] = __float2bfloat16(v[j] - __bfloat162float(hi[j]));
    }
}

// ---------------- cat1: A1' = split([mean | x]) ----------------
__global__ void cat1_split(const float* __restrict__ x) {
    int idx = blockIdx.x * blockDim.x + threadIdx.x;
    if (idx >= NN * 32) return;
    int n = idx >> 5, cb = (idx & 31) * 8;
    float v[8];
    if (cb < 128) {
        #pragma unroll
        for (int j = 0; j < 8; j++) v[j] = g_agg[n * 128 + cb + j];
    } else {
        #pragma unroll
        for (int j = 0; j < 8; j++) v[j] = x[n * 128 + (cb - 128) + j];
    }
    alignas(16) __nv_bfloat16 hi[8], lo[8];
    split8(v, hi, lo);
    __nv_bfloat16* base = g_A1 + (size_t)n * 768 + cb;
    *(uint4*)(base)       = *(uint4*)hi;
    *(uint4*)(base + 256) = *(uint4*)hi;
    *(uint4*)(base + 512) = *(uint4*)lo;
}

// ---------------- combine2: A3' = split(relu(mean(t) + s + b2)) ----------------
__global__ void combine2_split(const float* __restrict__ b2) {
    int idx = blockIdx.x * blockDim.x + threadIdx.x;
    if (idx >= NN * 16) return;
    int n = idx >> 4, cb = (idx & 15) * 8;
    float v[8];
    #pragma unroll
    for (int j = 0; j < 8; j++) {
        float a = g_agg[n * 128 + cb + j];
        float t = g_ts[(size_t)n * 256 + 128 + cb + j];
        v[j] = fmaxf(a + t + b2[cb + j], 0.f);
    }
    alignas(16) __nv_bfloat16 hi[8], lo[8];
    split8(v, hi, lo);
    __nv_bfloat16* base = g_A3 + (size_t)n * 384 + cb;
    *(uint4*)(base)       = *(uint4*)hi;
    *(uint4*)(base + 128) = *(uint4*)hi;
    *(uint4*)(base + 256) = *(uint4*)lo;
}

// ---------------- final: v = mean3 + u_r + b3 ; log_softmax over 64 ----------------
__global__ void final_kernel(const float* __restrict__ b3, float* __restrict__ out) {
    int gwarp = (blockIdx.x * blockDim.x + threadIdx.x) >> 5;
    int lane = threadIdx.x & 31;
    if (gwarp >= NN) return;
    float v0 = g_agg3[gwarp * 64 + lane]      + g_u[gwarp * 128 + 64 + lane] + b3[lane];
    float v1 = g_agg3[gwarp * 64 + 32 + lane] + g_u[gwarp * 128 + 96 + lane] + b3[32 + lane];
    float m = fmaxf(v0, v1);
    #pragma unroll
    for (int o = 16; o; o >>= 1) m = fmaxf(m, __shfl_xor_sync(0xffffffffu, m, o));
    float sum = expf(v0 - m) + expf(v1 - m);
    #pragma unroll
    for (int o = 16; o; o >>= 1) sum += __shfl_xor_sync(0xffffffffu, sum, o);
    float lse = m + logf(sum);
    out[gwarp * 64 + lane]      = v0 - lse;
    out[gwarp * 64 + 32 + lane] = v1 - lse;
}

// ---------------- wmma bf16 GEMM, 2-stage cp.async pipeline ----------------
#define LDT 72
#define TILE_B (128 * LDT * 2)
#define GEMM_SMEM (2 * 2 * TILE_B)   // 73728 bytes

__global__ __launch_bounds__(256, 2) void gemm_wmma(
    const __nv_bfloat16* __restrict__ A, const __nv_bfloat16* __restrict__ Bt,
    float* __restrict__ Cf, __nv_bfloat16* __restrict__ Chl,
    const float* __restrict__ bias, int M, int Nfull, int K3, int mode, int relu)
{
    extern __shared__ __align__(16) uint8_t dynsmem[];
    float* stage = (float*)dynsmem;   // epilogue overlay (128 x 68 f32)
    const int LDS = 68;

    const int tid = threadIdx.x;
    const int wid = tid >> 5;
    const int wr = wid >> 2, wc = wid & 3;
    const int blockRow = blockIdx.y * 128;
    const int n0 = blockIdx.x * 128;

    wmma::fragment<wmma::accumulator, 16, 16, 16, float> acc[4][2];
    #pragma unroll
    for (int i = 0; i < 4; i++)
        #pragma unroll
        for (int j = 0; j < 2; j++) wmma::fill_fragment(acc[i][j], 0.f);

    const int NC = K3 >> 6;

    auto issue = [&](int c, int st) {
        uint8_t* bufA = dynsmem + st * 2 * TILE_B;
        uint8_t* bufB = bufA + TILE_B;
        #pragma unroll
        for (int i = 0; i < 4; i++) {
            int idx = tid + i * 256;
            int r = idx >> 3, c16 = idx & 7;
            int grow = blockRow + r; if (grow >= M) grow = M - 1;
            cp_async16(smem_u32(bufA + (r * LDT + c16 * 8) * 2),
                       A + (size_t)grow * K3 + (size_t)c * 64 + c16 * 8);
            int nrow = n0 + r;
            cp_async16(smem_u32(bufB + (r * LDT + c16 * 8) * 2),
                       Bt + (size_t)nrow * K3 + (size_t)c * 64 + c16 * 8);
        }
        cp_commit();
    };

    issue(0, 0);
    for (int c = 0; c < NC; c++) {
        int st = c & 1;
        if (c + 1 < NC) { issue(c + 1, (c + 1) & 1); cp_wait<1>(); }
        else            { cp_wait<0>(); }
        __syncthreads();
        __nv_bfloat16* sA = (__nv_bfloat16*)(dynsmem + st * 2 * TILE_B);
        __nv_bfloat16* sB = (__nv_bfloat16*)(dynsmem + st * 2 * TILE_B + TILE_B);
        #pragma unroll
        for (int k = 0; k < 4; k++) {
            wmma::fragment<wmma::matrix_a, 16, 16, 16, __nv_bfloat16, wmma::row_major> af[4];
            wmma::fragment<wmma::matrix_b, 16, 16, 16, __nv_bfloat16, wmma::col_major> bf[2];
            #pragma unroll
            for (int i = 0; i < 4; i++)
                wmma::load_matrix_sync(af[i], sA + (wr * 64 + i * 16) * LDT + k * 16, LDT);
            #pragma unroll
            for (int j = 0; j < 2; j++)
                wmma::load_matrix_sync(bf[j], sB + (wc * 32 + j * 16) * LDT + k * 16, LDT);
            #pragma unroll
            for (int i = 0; i < 4; i++)
                #pragma unroll
                for (int j = 0; j < 2; j++)
                    wmma::mma_sync(acc[i][j], af[i], bf[j], acc[i][j]);
        }
        __syncthreads();
    }

    // epilogue: two passes of 64 N-columns through the smem stage
    for (int p = 0; p < 2; p++) {
        __syncthreads();
        if ((wc >> 1) == p) {
            #pragma unroll
            for (int i = 0; i < 4; i++)
                #pragma unroll
                for (int j = 0; j < 2; j++)
                    wmma::store_matrix_sync(
                        stage + (wr * 64 + i * 16) * LDS + (wc & 1) * 32 + j * 16,
                        acc[i][j], LDS, wmma::mem_row_major);
        }
        __syncthreads();
        int r = tid >> 1, h = tid & 1;
        int grow = blockRow + r;
        if (grow < M) {
            #pragma unroll
            for (int g = 0; g < 4; g++) {
                int cl = h * 32 + g * 8;
                int gcol = n0 + p * 64 + cl;
                float v[8];
                #pragma unroll
                for (int j = 0; j < 8; j++) {
                    v[j] = stage[r * LDS + cl + j];
                    if (bias) v[j] += __ldg(&bias[gcol + j]);
                    if (relu) v[j] = fmaxf(v[j], 0.f);
                }
                if (mode == 0) {
                    float4* pp = (float4*)(Cf + (size_t)grow * Nfull + gcol);
                    pp[0] = make_float4(v[0], v[1], v[2], v[3]);
                    pp[1] = make_float4(v[4], v[5], v[6], v[7]);
                } else {
                    alignas(16) __nv_bfloat16 hi[8], lo[8];
                    split8(v, hi, lo);
                    __nv_bfloat16* base = Chl + (size_t)grow * (3 * Nfull) + gcol;
                    *(uint4*)(base)             = *(uint4*)hi;
                    *(uint4*)(base + Nfull)     = *(uint4*)hi;
                    *(uint4*)(base + 2 * Nfull) = *(uint4*)lo;
                }
            }
        }
    }
}

// ---------------- launch ----------------
extern "C" void kernel_launch(void* const* d_in, const int* in_sizes, int n_in,
                              void* d_out, int out_size) {
    const float* x   = (const float*)d_in[0];
    const int*   ei  = (const int*)d_in[1];     // int32 edge_index [2, E]
    const float* W1l = (const float*)d_in[2];
    const float* W1r = (const float*)d_in[3];
    const float* b1  = (const float*)d_in[4];
    const float* W2l = (const float*)d_in[5];
    const float* W2r = (const float*)d_in[6];
    const float* b2  = (const float*)d_in[7];
    const float* W3l = (const float*)d_in[8];
    const float* W3r = (const float*)d_in[9];
    const float* b3  = (const float*)d_in[10];
    float* out = (float*)d_out;
    int E = in_sizes[1] / 2;
    (void)n_in; (void)out_size;

    void *p_ts, *p_u, *p_A1, *p_A2, *p_A3, *p_B1t, *p_B2t, *p_B3t, *p_agg, *p_agg3;
    cudaGetSymbolAddress(&p_ts, g_ts);
    cudaGetSymbolAddress(&p_u, g_u);
    cudaGetSymbolAddress(&p_A1, g_A1);
    cudaGetSymbolAddress(&p_A2, g_A2);
    cudaGetSymbolAddress(&p_A3, g_A3);
    cudaGetSymbolAddress(&p_B1t, g_B1t);
    cudaGetSymbolAddress(&p_B2t, g_B2t);
    cudaGetSymbolAddress(&p_B3t, g_B3t);
    cudaGetSymbolAddress(&p_agg, g_agg);
    cudaGetSymbolAddress(&p_agg3, g_agg3);

    cudaFuncSetAttribute(gemm_wmma, cudaFuncAttributeMaxDynamicSharedMemorySize, GEMM_SMEM);

    const int MT = (NN + 127) / 128;   // 782 M-tiles

    // ---- CSR build (once; shared by all 3 aggregations) ----
    zero_int2<<<(NN + 255) / 256, 256>>>();
    count_kernel<<<(E + 255) / 256, 256>>>(ei, E);
    inv_kernel<<<(NN + 255) / 256, 256>>>();
    scan1_kernel<<<NSCAN, SCAN_BLK>>>();
    scan2_kernel<<<1, SCAN_BLK>>>();
    scan3_kernel<<<(NN + 255) / 256, 256>>>();
    fill_kernel<<<(E + 255) / 256, 256>>>(ei, E);

    build_b1t<<<(256 * 768 + 255) / 256, 256>>>(W1l, W1r);
    build_b2t<<<(256 * 768 + 255) / 256, 256>>>(W2l, W2r);
    build_b3t<<<(128 * 384 + 255) / 256, 256>>>(W3l, W3r);

    // ---- layer 1: mean(x) via gather, cat+split, GEMM1 -> A2 ----
    gather_mean<32><<<(NN * 32 + 255) / 256, 256>>>(x, 32, (float*)p_agg);
    cat1_split<<<(NN * 32 + 255) / 256, 256>>>(x);
    gemm_wmma<<<dim3(2, MT), 256, GEMM_SMEM>>>(
        (const __nv_bfloat16*)p_A1, (const __nv_bfloat16*)p_B1t,
        nullptr, (__nv_bfloat16*)p_A2, b1, NN, 256, 768, 1, 1);

    // ---- layer 2: GEMM2 -> [t|s], mean(t) via gather, combine+split -> A3 ----
    gemm_wmma<<<dim3(2, MT), 256, GEMM_SMEM>>>(
        (const __nv_bfloat16*)p_A2, (const __nv_bfloat16*)p_B2t,
        (float*)p_ts, nullptr, nullptr, NN, 256, 768, 0, 0);
    gather_mean<32><<<(NN * 32 + 255) / 256, 256>>>((const float*)p_ts, 64, (float*)p_agg);
    combine2_split<<<(NN * 16 + 255) / 256, 256>>>(b2);

    // ---- layer 3: GEMM3 -> [u_l|u_r], mean(u_l) via gather, final ----
    gemm_wmma<<<dim3(1, MT), 256, GEMM_SMEM>>>(
        (const __nv_bfloat16*)p_A3, (const __nv_bfloat16*)p_B3t,
        (float*)p_u, nullptr, nullptr, NN, 128, 384, 0, 0);
    gather_mean<16><<<(NN * 16 + 255) / 256, 256>>>((const float*)p_u, 32, (float*)p_agg3);
    final_kernel<<<(NN * 32 + 255) / 256, 256>>>(b3, out);
}